// round 11
// baseline (speedup 1.0000x reference)
#include <cuda_runtime.h>

#define FULLMASK 0xFFFFFFFFu

constexpr int   G     = 64;          // 64x64 grid of 16px cells
constexpr float CELL  = 16.0f;
constexpr float CELLI = 1.0f / 16.0f;
constexpr int   NC    = G * G;
constexpr int   R     = 2;           // replicated sub-counters per cell
constexpr int   SUB   = 40;          // capacity per replica; lambda=8 -> P(>40) ~ 1e-18
constexpr int   CAP   = R * SUB;     // 80 slots per cell
constexpr int   K     = 9;
constexpr int   WARPS = 2;
constexpr int   CHUNK = 6;           // 6*32 = 192 capacity; P(T>192) ~ 3e-5
constexpr int   TPW   = 2;           // targets per warp (ILP doubling)

__device__ int    g_count[NC * R];     // [cell][replica]
__device__ float4 g_cells[NC * CAP];   // x, y, bitcast(orig idx), pad

__global__ void bin_k(const float* __restrict__ p, int N) {
    int i = blockIdx.x * blockDim.x + threadIdx.x;
    if (i >= N) return;
    float2 c = reinterpret_cast<const float2*>(p)[i * 3 + 1];  // floats 6i+2, 6i+3
    int cx = min(G - 1, max(0, (int)(c.x * CELLI)));
    int cy = min(G - 1, max(0, (int)(c.y * CELLI)));
    int cell = cy * G + cx;
    int r = i & (R - 1);
    int pos = atomicAdd(&g_count[cell * R + r], 1);
    if (pos < SUB)
        g_cells[cell * CAP + r * SUB + pos] = make_float4(c.x, c.y, __int_as_float(i), 0.f);
}

__global__ __launch_bounds__(WARPS * 32)
void atss_search_k(const float* __restrict__ pbox,
                   const float* __restrict__ tgt,
                   float* __restrict__ out, int NT)
{
    const int lane = threadIdx.x & 31;
    const int w = blockIdx.x * WARPS + (threadIdx.x >> 5);
    if (w * TPW >= NT) return;

    const float INF = __int_as_float(0x7f800000);

    int   tid[2];  bool act[2];
    float tx[2], ty[2], gw[2], gh[2];
    int   tcx[2], tcy[2];
    #pragma unroll
    for (int g = 0; g < TPW; g++) {
        tid[g] = w * TPW + g;
        act[g] = (tid[g] < NT);
        int tt = act[g] ? tid[g] : 0;
        float2 tc = *reinterpret_cast<const float2*>(tgt + tt * 6 + 2);  // independent loads
        float2 sz = *reinterpret_cast<const float2*>(tgt + tt * 6 + 4);
        tx[g] = tc.x; ty[g] = tc.y; gw[g] = sz.x; gh[g] = sz.y;
        tcx[g] = min(G - 1, max(0, (int)(tx[g] * CELLI)));
        tcy[g] = min(G - 1, max(0, (int)(ty[g] * CELLI)));
    }

    // ---- 3x3 cell info for both targets: 18 independent int2 count loads ----
    int cb[2][9], sa[2][9], pref[2][10], T[2];
    #pragma unroll
    for (int g = 0; g < TPW; g++) {
        #pragma unroll
        for (int j = 0; j < 9; j++) {
            int x = tcx[g] + (j % 3) - 1;
            int y = tcy[g] + (j / 3) - 1;
            bool ok = act[g] & (x >= 0) & (x < G) & (y >= 0) & (y < G);
            int c = ok ? (y * G + x) : 0;
            cb[g][j] = c * CAP;
            int2 q = ok ? __ldg(reinterpret_cast<const int2*>(g_count + c * R))
                        : make_int2(0, 0);
            int c0 = min(q.x, SUB), c1 = min(q.y, SUB);
            sa[g][j] = c0;
            pref[g][j] = c0 + c1;     // temporarily cnt; prefixed below
        }
        int run = 0;
        #pragma unroll
        for (int j = 0; j < 9; j++) { int cj = pref[g][j]; pref[g][j] = run; run += cj; }
        pref[g][9] = run;
        T[g] = run;
    }

    unsigned long long sel[2] = { ~0ull, ~0ull };
    unsigned D9bits[2] = { 0xFFFFFFFFu, 0xFFFFFFFFu };
    bool hot[2];
    #pragma unroll
    for (int g = 0; g < TPW; g++) hot[g] = act[g] && (T[g] <= 32 * CHUNK);

    // ---- hot path for both targets, phase-interleaved for 2x ILP/MLP ----
    unsigned long long key[2][CHUNK];
    {
        float4 pts[2][CHUNK]; bool val[2][CHUNK];
        #pragma unroll
        for (int c = 0; c < CHUNK; c++) {
            #pragma unroll
            for (int g = 0; g < TPW; g++) {
                int v = c * 32 + lane;
                val[g][c] = hot[g] && (v < T[g]);
                int basei = cb[g][0], pr = 0, a1 = sa[g][0];
                #pragma unroll
                for (int jj = 1; jj < 9; jj++) {
                    bool ge = (v >= pref[g][jj]);
                    basei = ge ? cb[g][jj]   : basei;
                    pr    = ge ? pref[g][jj] : pr;
                    a1    = ge ? sa[g][jj]   : a1;
                }
                int u = v - pr;
                int addr = basei + ((u >= a1) ? (SUB + u - a1) : u);
                if (val[g][c]) pts[g][c] = __ldg(&g_cells[addr]);   // interleaved LDGs
            }
        }
        #pragma unroll
        for (int g = 0; g < TPW; g++) {
            #pragma unroll
            for (int c = 0; c < CHUNK; c++) {
                if (val[g][c]) {
                    float dx = tx[g] - pts[g][c].x;
                    float dy = ty[g] - pts[g][c].y;
                    float d2 = fmaf(dy, dy, dx * dx);   // identical fp expr to verified kernels
                    key[g][c] = ((unsigned long long)__float_as_uint(d2) << 32)
                              | (unsigned)__float_as_int(pts[g][c].z);
                } else {
                    key[g][c] = ~0ull;                  // pad sorts last
                }
            }
        }
    }

    // two independent 12-CE sorting networks (ascending)
    #pragma unroll
    for (int g = 0; g < TPW; g++) {
        auto CE = [&](int a, int b) {
            unsigned long long ka = key[g][a], kb = key[g][b];
            key[g][a] = ka < kb ? ka : kb;
            key[g][b] = ka < kb ? kb : ka;
        };
        CE(1,2); CE(4,5); CE(0,2); CE(3,5); CE(0,1); CE(3,4);
        CE(2,5); CE(0,3); CE(1,4); CE(2,4); CE(1,3); CE(2,3);
    }

    // 9 extraction rounds; both targets' REDUX pairs issued per round (independent)
    #pragma unroll
    for (int r = 0; r < K; r++) {
        #pragma unroll
        for (int g = 0; g < TPW; g++) {
            unsigned hi = (unsigned)(key[g][0] >> 32);
            unsigned lo = (unsigned)key[g][0];
            unsigned m1 = __reduce_min_sync(FULLMASK, hi);
            unsigned iv = (hi == m1) ? lo : 0xFFFFFFFFu;
            unsigned m2 = __reduce_min_sync(FULLMASK, iv);
            if (lane == r) sel[g] = ((unsigned long long)m1 << 32) | m2;
            if (r == K - 1) D9bits[g] = m1;
            if (hi == m1 && lo == m2) {     // unique owner for real keys
                #pragma unroll
                for (int j = 0; j < CHUNK - 1; j++) key[g][j] = key[g][j + 1];
                key[g][CHUNK - 1] = ~0ull;
            }
        }
    }

    // ---- stop bounds; fallback per target (cold) ----
    #pragma unroll
    for (int g = 0; g < TPW; g++) {
        if (!act[g]) continue;
        bool stop = false;
        if (hot[g]) {
            float D9 = __uint_as_float(D9bits[g]);
            int x0 = max(tcx[g] - 1, 0), x1 = min(tcx[g] + 1, G - 1);
            int y0 = max(tcy[g] - 1, 0), y1 = min(tcy[g] + 1, G - 1);
            float m = INF;
            if (x0 > 0)     m = fminf(m, tx[g] - (float)x0 * CELL);
            if (x1 < G - 1) m = fminf(m, (float)(x1 + 1) * CELL - tx[g]);
            if (y0 > 0)     m = fminf(m, ty[g] - (float)y0 * CELL);
            if (y1 < G - 1) m = fminf(m, (float)(y1 + 1) * CELL - ty[g]);
            m *= 0.999f;    // conservative; false on NaN/INF D9 -> fallback
            stop = (m > 0.f && m * m > D9);
        }
        if (stop) continue;

        // fallback: box rescan from scratch, lane-per-cell (verified machinery)
        float txg = tx[g], tyg = ty[g];
        float bd[K]; int bi[K];
        auto insertPt = [&](float4 c) {
            float dx = txg - c.x;
            float dy = tyg - c.y;
            float d2 = fmaf(dy, dy, dx * dx);
            int   ci = __float_as_int(c.z);
            if (d2 < bd[K - 1] || (d2 == bd[K - 1] && ci < bi[K - 1])) {
                float cd = d2; int cj = ci;
                #pragma unroll
                for (int j = 0; j < K; j++) {
                    bool lt = (cd < bd[j]) || (cd == bd[j] && cj < bi[j]);
                    if (lt) {
                        float td = bd[j]; bd[j] = cd; cd = td;
                        int   ti = bi[j]; bi[j] = cj; cj = ti;
                    }
                }
            }
        };
        auto merge = [&]() {
            unsigned long long kk[K];
            #pragma unroll
            for (int j = 0; j < K; j++)
                kk[j] = ((unsigned long long)__float_as_uint(bd[j]) << 32) | (unsigned)bi[j];
            unsigned long long cur = kk[0];
            #pragma unroll
            for (int r = 0; r < K; r++) {
                unsigned long long mm = cur;
                #pragma unroll
                for (int o = 16; o; o >>= 1) {
                    unsigned long long v = __shfl_xor_sync(FULLMASK, mm, o);
                    if (v < mm) mm = v;
                }
                if (lane == r) sel[g] = mm;
                if (cur == mm) {
                    #pragma unroll
                    for (int j = 0; j < K - 1; j++) kk[j] = kk[j + 1];
                    kk[K - 1] = ~0ull;
                    cur = kk[0];
                }
            }
        };

        for (int r = 2; ; r++) {
            int x0 = max(tcx[g] - r, 0), x1 = min(tcx[g] + r, G - 1);
            int y0 = max(tcy[g] - r, 0), y1 = min(tcy[g] + r, G - 1);
            int W = x1 - x0 + 1;
            int ncells = W * (y1 - y0 + 1);

            #pragma unroll
            for (int j = 0; j < K; j++) { bd[j] = INF; bi[j] = 0x7fffffff; }

            for (int cc = lane; cc < ncells; cc += 32) {
                int yy = y0 + cc / W;
                int xx = x0 + cc % W;
                int cell = yy * G + xx;
                int2 q = __ldg(reinterpret_cast<const int2*>(g_count + cell * R));
                const float4* bp = g_cells + cell * CAP;
                #pragma unroll
                for (int rr = 0; rr < R; rr++) {
                    int cn = min(rr == 0 ? q.x : q.y, SUB);
                    const float4* sp = bp + rr * SUB;
                    int s = 0;
                    for (; s + 2 <= cn; s += 2) {
                        float4 p0 = __ldg(sp + s);
                        float4 p1 = __ldg(sp + s + 1);
                        insertPt(p0); insertPt(p1);
                    }
                    for (; s < cn; s++) insertPt(__ldg(sp + s));
                }
            }

            merge();
            if (x0 == 0 && y0 == 0 && x1 == G - 1 && y1 == G - 1) break;
            unsigned d9b = __shfl_sync(FULLMASK, (unsigned)(sel[g] >> 32), 8);
            float D9f = __uint_as_float(d9b);
            float mf = INF;
            if (x0 > 0)     mf = fminf(mf, txg - (float)x0 * CELL);
            if (x1 < G - 1) mf = fminf(mf, (float)(x1 + 1) * CELL - txg);
            if (y0 > 0)     mf = fminf(mf, tyg - (float)y0 * CELL);
            if (y1 < G - 1) mf = fminf(mf, (float)(y1 + 1) * CELL - tyg);
            mf *= 0.999f;
            if (mf > 0.f && mf * mf > D9f) break;
        }
    }

    // ---- epilogue gather (both targets' loads in flight together) ----
    float cx[2], cy[2], cw_[2], ch_[2];
    #pragma unroll
    for (int g = 0; g < TPW; g++) {
        cx[g] = 0.f; cy[g] = 0.f; cw_[g] = 0.f; ch_[g] = 0.f;
        if (act[g] && lane < K) {
            int idx = (int)(sel[g] & 0xffffffffull);
            float2 pc  = *reinterpret_cast<const float2*>(pbox + (size_t)idx * 6 + 2);
            float2 psz = *reinterpret_cast<const float2*>(pbox + (size_t)idx * 6 + 4);
            cx[g] = pc.x; cy[g] = pc.y; cw_[g] = psz.x; ch_[g] = psz.y;
        }
    }

    // ---- epilogue math: GIoU + mean/var(ddof=1), bit-identical fp order ----
    #pragma unroll
    for (int g = 0; g < TPW; g++) {
        if (!act[g]) continue;
        float b1x1 = tx[g] - gw[g] * 0.5f, b1x2 = tx[g] + gw[g] * 0.5f;
        float b1y1 = ty[g] - gh[g] * 0.5f, b1y2 = ty[g] + gh[g] * 0.5f;
        float b2x1 = cx[g] - cw_[g] * 0.5f, b2x2 = cx[g] + cw_[g] * 0.5f;
        float b2y1 = cy[g] - ch_[g] * 0.5f, b2y2 = cy[g] + ch_[g] * 0.5f;
        float iw = fmaxf(fminf(b1x2, b2x2) - fmaxf(b1x1, b2x1), 0.f);
        float ih = fmaxf(fminf(b1y2, b2y2) - fmaxf(b1y1, b2y1), 0.f);
        float inter = iw * ih;
        float w1 = b1x2 - b1x1, h1 = b1y2 - b1y1;
        float w2 = b2x2 - b2x1, h2 = b2y2 - b2y1;
        float uni = ((w1 * h1 + 1e-16f) + w2 * h2) - inter;
        float iou = __fdiv_rn(inter, uni);
        float ccw = fmaxf(b1x2, b2x2) - fminf(b1x1, b2x1);
        float cch = fmaxf(b1y2, b2y2) - fminf(b1y1, b2y1);
        float carea = ccw * cch + 1e-16f;
        float gv = iou - __fdiv_rn(carea - uni, carea);

        float s = 0.f;
        #pragma unroll
        for (int j = 0; j < K; j++) s += __shfl_sync(FULLMASK, gv, j);
        float mean = __fdiv_rn(s, 9.0f);
        float v = 0.f;
        #pragma unroll
        for (int j = 0; j < K; j++) {
            float gj = __shfl_sync(FULLMASK, gv, j);
            float d = gj - mean;
            v += d * d;
        }
        float var = __fdiv_rn(v, 8.0f);
        float thr = mean + var;

        if (lane < K) {
            float msk = (gv > thr) ? 1.0f : 0.0f;
            float4 o = make_float4(cx[g] * msk, cy[g] * msk, cw_[g] * msk, ch_[g] * msk);
            *reinterpret_cast<float4*>(out + ((size_t)tid[g] * K + lane) * 4) = o;
        }
    }
}

extern "C" void kernel_launch(void* const* d_in, const int* in_sizes, int n_in,
                              void* d_out, int out_size) {
    const float* pbox = (const float*)d_in[0];
    const float* tgt  = (const float*)d_in[1];
    int N  = in_sizes[0] / 6;
    int NT = in_sizes[1] / 6;

    void* cnt_ptr = nullptr;
    cudaGetSymbolAddress(&cnt_ptr, g_count);
    cudaMemsetAsync(cnt_ptr, 0, NC * R * sizeof(int));   // memset node, graph-capturable

    bin_k<<<(N + 255) / 256, 256>>>(pbox, N);

    int tpb = WARPS * TPW;                                // targets per block
    int blocks = (NT + tpb - 1) / tpb;
    atss_search_k<<<blocks, WARPS * 32>>>(pbox, tgt, (float*)d_out, NT);
}

// round 14
// speedup vs baseline: 1.0174x; 1.0174x over previous
#include <cuda_runtime.h>

#define FULLMASK 0xFFFFFFFFu

constexpr int   G     = 64;          // 64x64 grid of 16px cells
constexpr float CELL  = 16.0f;
constexpr float CELLI = 1.0f / 16.0f;
constexpr int   NC    = G * G;
constexpr int   R     = 2;           // replicated sub-counters per cell
constexpr int   SUB   = 40;          // capacity per replica; lambda=8 -> P(>40) ~ 1e-18
constexpr int   CAP   = R * SUB;     // 80 slots per cell
constexpr int   K     = 9;
constexpr int   WARPS = 2;           // warps per block (1 target per warp)
constexpr int   CHUNK = 6;           // 6*32 = 192 capacity; P(T>192) ~ 3e-5

__device__ int      g_count[NC * R];    // [cell][replica]
__device__ float4   g_cells[NC * CAP];  // x, y, bitcast(orig idx), pad
__device__ unsigned g_bar;              // monotonic barrier ticket (never reset; replay-safe)

// Ticket grid barrier: counter only ever increases; each barrier instance adds
// exactly gridDim.x, so the base stays a multiple of gridDim.x across graph replays.
// Requires all blocks co-resident: 1024 blocks x 64 thr @ ~80 regs -> 7 blocks/SM
// (35.8K regs of 64K), guaranteed resident on 148 SMs.
__device__ __forceinline__ void grid_barrier() {
    __syncthreads();
    if (threadIdx.x == 0) {
        __threadfence();                               // release block's writes device-wide
        unsigned ticket = atomicAdd(&g_bar, 1u);
        unsigned target = ticket / gridDim.x * gridDim.x + gridDim.x;
        while (*(volatile unsigned*)&g_bar < target) { __nanosleep(64); }
        __threadfence();                               // acquire others' writes
    }
    __syncthreads();
}

__global__ __launch_bounds__(WARPS * 32)
void atss_fused_k(const float* __restrict__ pbox,
                  const float* __restrict__ tgt,
                  float* __restrict__ out, int N, int NT)
{
    // ================= phase 1: bin (one point per thread; guard loop for odd N) ==
    {
        int stride = gridDim.x * blockDim.x;
        for (int i = blockIdx.x * blockDim.x + threadIdx.x; i < N; i += stride) {
            float2 c = reinterpret_cast<const float2*>(pbox)[i * 3 + 1];  // floats 6i+2,6i+3
            int cx = min(G - 1, max(0, (int)(c.x * CELLI)));
            int cy = min(G - 1, max(0, (int)(c.y * CELLI)));
            int cell = cy * G + cx;
            int r = i & (R - 1);
            int pos = atomicAdd(&g_count[cell * R + r], 1);
            if (pos < SUB)
                g_cells[cell * CAP + r * SUB + pos] =
                    make_float4(c.x, c.y, __int_as_float(i), 0.f);
        }
    }

    grid_barrier();

    // ================= phase 2: search (1 warp per target) =======================
    const int lane = threadIdx.x & 31;
    const int t = blockIdx.x * WARPS + (threadIdx.x >> 5);
    if (t >= NT) return;

    const float INF = __int_as_float(0x7f800000);
    float2 tc = *reinterpret_cast<const float2*>(tgt + t * 6 + 2);
    float2 ts = *reinterpret_cast<const float2*>(tgt + t * 6 + 4);
    const float tx = tc.x, ty = tc.y;
    const int tcx = min(G - 1, max(0, (int)(tx * CELLI)));
    const int tcy = min(G - 1, max(0, (int)(ty * CELLI)));

    // ---- gather 3x3 cell info: one aligned int2 count load per cell ----
    int cb[9]; int sa[9]; int pref[10];
    {
        int cnt[9];
        #pragma unroll
        for (int j = 0; j < 9; j++) {
            int x = tcx + (j % 3) - 1;
            int y = tcy + (j / 3) - 1;
            bool ok = (x >= 0) & (x < G) & (y >= 0) & (y < G);
            int c = ok ? (y * G + x) : 0;
            cb[j] = c * CAP;
            int2 q = ok ? __ldg(reinterpret_cast<const int2*>(g_count + c * R))
                        : make_int2(0, 0);
            int c0 = min(q.x, SUB), c1 = min(q.y, SUB);
            cnt[j] = c0 + c1;
            sa[j]  = c0;
        }
        pref[0] = 0;
        #pragma unroll
        for (int j = 0; j < 9; j++) pref[j + 1] = pref[j] + cnt[j];
    }
    const int T = pref[9];

    unsigned long long sel = ~0ull;
    bool stop = false;

    if (T <= 32 * CHUNK) {
        // ---- hot path: batched loads, lane sort, REDUX extraction ----
        unsigned long long key[CHUNK];
        {
            float4 pts[CHUNK]; bool val[CHUNK];
            auto mapLoad = [&](int c) {
                int v = c * 32 + lane;
                val[c] = (v < T);
                int basei = cb[0], pr = 0, a1 = sa[0];
                #pragma unroll
                for (int jj = 1; jj < 9; jj++) {
                    bool ge = (v >= pref[jj]);
                    basei = ge ? cb[jj]   : basei;
                    pr    = ge ? pref[jj] : pr;
                    a1    = ge ? sa[jj]   : a1;
                }
                int u = v - pr;
                int addr = basei + ((u >= a1) ? (SUB + u - a1) : u);
                if (val[c]) pts[c] = __ldg(&g_cells[addr]);   // independent LDGs, high MLP
            };
            #pragma unroll
            for (int c = 0; c < 4; c++) mapLoad(c);
            if (T > 128) {              // warp-uniform: skip last 2 chunks when unneeded
                mapLoad(4); mapLoad(5);
            } else {
                val[4] = false; val[5] = false;
            }
            #pragma unroll
            for (int c = 0; c < CHUNK; c++) {
                if (val[c]) {
                    float dx = tx - pts[c].x;
                    float dy = ty - pts[c].y;
                    float d2 = fmaf(dy, dy, dx * dx);   // identical fp expr to verified kernels
                    key[c] = ((unsigned long long)__float_as_uint(d2) << 32)
                           | (unsigned)__float_as_int(pts[c].z);
                } else {
                    key[c] = ~0ull;                     // pad sorts last
                }
            }
        }

        // optimal 12-CE sorting network for 6 elements (ascending)
        auto CE = [&](int a, int b) {
            unsigned long long ka = key[a], kb = key[b];
            key[a] = ka < kb ? ka : kb;
            key[b] = ka < kb ? kb : ka;
        };
        CE(1,2); CE(4,5); CE(0,2); CE(3,5); CE(0,1); CE(3,4);
        CE(2,5); CE(0,3); CE(1,4); CE(2,4); CE(1,3); CE(2,3);

        // 9 extraction rounds: exact lex-min via two hardware REDUX.MIN ops
        unsigned D9bits = 0xFFFFFFFFu;
        #pragma unroll
        for (int r = 0; r < K; r++) {
            unsigned hi = (unsigned)(key[0] >> 32);
            unsigned lo = (unsigned)key[0];
            unsigned m1 = __reduce_min_sync(FULLMASK, hi);
            unsigned iv = (hi == m1) ? lo : 0xFFFFFFFFu;
            unsigned m2 = __reduce_min_sync(FULLMASK, iv);
            if (lane == r) sel = ((unsigned long long)m1 << 32) | m2;
            if (r == K - 1) D9bits = m1;
            if (hi == m1 && lo == m2) {     // unique owner for real keys
                #pragma unroll
                for (int j = 0; j < CHUNK - 1; j++) key[j] = key[j + 1];
                key[CHUNK - 1] = ~0ull;
            }
        }

        // r=1 stop bound (conservative). NaN/INF D9 -> stop stays false -> fallback.
        float D9 = __uint_as_float(D9bits);
        int x0 = max(tcx - 1, 0), x1 = min(tcx + 1, G - 1);
        int y0 = max(tcy - 1, 0), y1 = min(tcy + 1, G - 1);
        float m = INF;
        if (x0 > 0)     m = fminf(m, tx - (float)x0 * CELL);
        if (x1 < G - 1) m = fminf(m, (float)(x1 + 1) * CELL - tx);
        if (y0 > 0)     m = fminf(m, ty - (float)y0 * CELL);
        if (y1 < G - 1) m = fminf(m, (float)(y1 + 1) * CELL - ty);
        m *= 0.999f;
        stop = (m > 0.f && m * m > D9);
    }

    if (!stop) {
        // ---- fallback: box rescan from scratch, lane-per-cell (cold) ----
        float bd[K]; int bi[K];

        auto insertPt = [&](float4 c) {
            float dx = tx - c.x;
            float dy = ty - c.y;
            float d2 = fmaf(dy, dy, dx * dx);
            int   ci = __float_as_int(c.z);
            if (d2 < bd[K - 1] || (d2 == bd[K - 1] && ci < bi[K - 1])) {
                float cd = d2; int cj = ci;
                #pragma unroll
                for (int j = 0; j < K; j++) {
                    bool lt = (cd < bd[j]) || (cd == bd[j] && cj < bi[j]);
                    if (lt) {
                        float td = bd[j]; bd[j] = cd; cd = td;
                        int   ti = bi[j]; bi[j] = cj; cj = ti;
                    }
                }
            }
        };
        auto merge = [&]() {
            unsigned long long kk[K];
            #pragma unroll
            for (int j = 0; j < K; j++)
                kk[j] = ((unsigned long long)__float_as_uint(bd[j]) << 32) | (unsigned)bi[j];
            unsigned long long cur = kk[0];
            #pragma unroll
            for (int r = 0; r < K; r++) {
                unsigned long long mm = cur;
                #pragma unroll
                for (int o = 16; o; o >>= 1) {
                    unsigned long long v = __shfl_xor_sync(FULLMASK, mm, o);
                    if (v < mm) mm = v;
                }
                if (lane == r) sel = mm;
                if (cur == mm) {
                    #pragma unroll
                    for (int j = 0; j < K - 1; j++) kk[j] = kk[j + 1];
                    kk[K - 1] = ~0ull;
                    cur = kk[0];
                }
            }
        };

        for (int r = 2; ; r++) {
            int x0 = max(tcx - r, 0), x1 = min(tcx + r, G - 1);
            int y0 = max(tcy - r, 0), y1 = min(tcy + r, G - 1);
            int W = x1 - x0 + 1;
            int ncells = W * (y1 - y0 + 1);

            #pragma unroll
            for (int j = 0; j < K; j++) { bd[j] = INF; bi[j] = 0x7fffffff; }

            for (int cc = lane; cc < ncells; cc += 32) {
                int yy = y0 + cc / W;
                int xx = x0 + cc % W;
                int cell = yy * G + xx;
                int2 q = __ldg(reinterpret_cast<const int2*>(g_count + cell * R));
                const float4* bp = g_cells + cell * CAP;
                #pragma unroll
                for (int rr = 0; rr < R; rr++) {
                    int cn = min(rr == 0 ? q.x : q.y, SUB);
                    const float4* sp = bp + rr * SUB;
                    int s = 0;
                    for (; s + 2 <= cn; s += 2) {
                        float4 p0 = __ldg(sp + s);
                        float4 p1 = __ldg(sp + s + 1);
                        insertPt(p0); insertPt(p1);
                    }
                    for (; s < cn; s++) insertPt(__ldg(sp + s));
                }
            }

            merge();
            if (x0 == 0 && y0 == 0 && x1 == G - 1 && y1 == G - 1) break;  // full grid
            unsigned d9b = __shfl_sync(FULLMASK, (unsigned)(sel >> 32), 8);
            float D9f = __uint_as_float(d9b);
            float mf = INF;
            if (x0 > 0)     mf = fminf(mf, tx - (float)x0 * CELL);
            if (x1 < G - 1) mf = fminf(mf, (float)(x1 + 1) * CELL - tx);
            if (y0 > 0)     mf = fminf(mf, ty - (float)y0 * CELL);
            if (y1 < G - 1) mf = fminf(mf, (float)(y1 + 1) * CELL - ty);
            mf *= 0.999f;    // conservative margin; false on NaN/INF -> keep expanding
            if (mf > 0.f && mf * mf > D9f) break;
        }
    }

    // ---- epilogue gather (post-extraction, verified round-8 form) ----
    float cx = 0.f, cy = 0.f, cw_ = 0.f, ch_ = 0.f;
    if (lane < K) {
        int idx = (int)(sel & 0xffffffffull);
        float2 pc  = *reinterpret_cast<const float2*>(pbox + (size_t)idx * 6 + 2);
        float2 psz = *reinterpret_cast<const float2*>(pbox + (size_t)idx * 6 + 4);
        cx = pc.x; cy = pc.y; cw_ = psz.x; ch_ = psz.y;
    }

    // ---- epilogue: GIoU + mean/var(ddof=1) threshold (bit-identical fp order) ----
    float gx = tx, gy = ty;
    float gw = ts.x, gh = ts.y;

    float b1x1 = gx - gw * 0.5f, b1x2 = gx + gw * 0.5f;
    float b1y1 = gy - gh * 0.5f, b1y2 = gy + gh * 0.5f;
    float b2x1 = cx - cw_ * 0.5f, b2x2 = cx + cw_ * 0.5f;
    float b2y1 = cy - ch_ * 0.5f, b2y2 = cy + ch_ * 0.5f;
    float iw = fmaxf(fminf(b1x2, b2x2) - fmaxf(b1x1, b2x1), 0.f);
    float ih = fmaxf(fminf(b1y2, b2y2) - fmaxf(b1y1, b2y1), 0.f);
    float inter = iw * ih;
    float w1 = b1x2 - b1x1, h1 = b1y2 - b1y1;
    float w2 = b2x2 - b2x1, h2 = b2y2 - b2y1;
    float uni = ((w1 * h1 + 1e-16f) + w2 * h2) - inter;
    float iou = __fdiv_rn(inter, uni);
    float ccw = fmaxf(b1x2, b2x2) - fminf(b1x1, b2x1);
    float cch = fmaxf(b1y2, b2y2) - fminf(b1y1, b2y1);
    float carea = ccw * cch + 1e-16f;
    float g = iou - __fdiv_rn(carea - uni, carea);

    float s = 0.f;
    #pragma unroll
    for (int j = 0; j < K; j++) s += __shfl_sync(FULLMASK, g, j);
    float mean = __fdiv_rn(s, 9.0f);
    float v = 0.f;
    #pragma unroll
    for (int j = 0; j < K; j++) {
        float gj = __shfl_sync(FULLMASK, g, j);
        float d = gj - mean;
        v += d * d;
    }
    float var = __fdiv_rn(v, 8.0f);
    float thr = mean + var;

    if (lane < K) {
        float msk = (g > thr) ? 1.0f : 0.0f;
        float4 o = make_float4(cx * msk, cy * msk, cw_ * msk, ch_ * msk);
        *reinterpret_cast<float4*>(out + ((size_t)t * K + lane) * 4) = o;
    }
}

extern "C" void kernel_launch(void* const* d_in, const int* in_sizes, int n_in,
                              void* d_out, int out_size) {
    const float* pbox = (const float*)d_in[0];
    const float* tgt  = (const float*)d_in[1];
    int N  = in_sizes[0] / 6;
    int NT = in_sizes[1] / 6;

    void* cnt_ptr = nullptr;
    cudaGetSymbolAddress(&cnt_ptr, g_count);
    cudaMemsetAsync(cnt_ptr, 0, NC * R * sizeof(int));   // memset node, graph-capturable

    // 1024 blocks x 64 threads: all co-resident (required by the grid barrier),
    // covers N=65536 bin points one per thread and NT=2048 targets one per warp.
    int blocks = (NT + WARPS - 1) / WARPS;
    atss_fused_k<<<blocks, WARPS * 32>>>(pbox, tgt, (float*)d_out, N, NT);
}

// round 15
// speedup vs baseline: 1.0233x; 1.0058x over previous
#include <cuda_runtime.h>

#define FULLMASK 0xFFFFFFFFu

constexpr int   G     = 64;          // 64x64 grid of 16px cells
constexpr float CELL  = 16.0f;
constexpr float CELLI = 1.0f / 16.0f;
constexpr int   NC    = G * G;
constexpr int   R     = 2;           // replicated sub-counters per cell
constexpr int   SUB   = 40;          // capacity per replica; lambda=8 -> P(>40) ~ 1e-18
constexpr int   CAP   = R * SUB;     // 80 slots per cell
constexpr int   K     = 9;
constexpr int   WARPS = 2;           // warps per block (1 target per warp)
constexpr int   CHUNK = 6;           // 6*32 = 192 capacity; P(T>192) ~ 3e-5

__device__ int      g_count[NC * R];    // [cell][replica]
__device__ float4   g_cells[NC * CAP];  // x, y, bitcast(orig idx), pad
__device__ unsigned g_bar;              // monotonic barrier ticket (never reset; replay-safe)

// Ticket grid barrier: counter only ever increases; each instance adds exactly
// gridDim.x, so the base stays a multiple of gridDim.x across graph replays.
// Co-residency: 1024 blocks x 64 thr at <=128 regs (launch_bounds(64,8)) ->
// 8 blocks/SM possible, 1184 slots >= 1024 blocks -> all resident, no deadlock.
__device__ __forceinline__ void grid_barrier() {
    __syncthreads();
    if (threadIdx.x == 0) {
        __threadfence();                               // release block's writes device-wide
        unsigned ticket = atomicAdd(&g_bar, 1u);
        unsigned target = ticket / gridDim.x * gridDim.x + gridDim.x;
        while (*(volatile unsigned*)&g_bar < target) { __nanosleep(32); }
        __threadfence();                               // acquire others' writes
    }
    __syncthreads();
}

__global__ __launch_bounds__(WARPS * 32, 8)   // cap 128 regs: NO spills (r14 bug: 64-reg clamp)
void atss_fused_k(const float* __restrict__ pbox,
                  const float* __restrict__ tgt,
                  float* __restrict__ out, int N, int NT)
{
    // ================= phase 1: bin (one point per thread) =======================
    {
        int stride = gridDim.x * blockDim.x;
        for (int i = blockIdx.x * blockDim.x + threadIdx.x; i < N; i += stride) {
            float2 c = reinterpret_cast<const float2*>(pbox)[i * 3 + 1];  // floats 6i+2,6i+3
            int cx = min(G - 1, max(0, (int)(c.x * CELLI)));
            int cy = min(G - 1, max(0, (int)(c.y * CELLI)));
            int cell = cy * G + cx;
            int r = i & (R - 1);
            int pos = atomicAdd(&g_count[cell * R + r], 1);
            if (pos < SUB)
                g_cells[cell * CAP + r * SUB + pos] =
                    make_float4(c.x, c.y, __int_as_float(i), 0.f);
        }
    }

    grid_barrier();

    // ================= phase 2: search (1 warp per target) =======================
    const int lane = threadIdx.x & 31;
    const int t = blockIdx.x * WARPS + (threadIdx.x >> 5);
    if (t >= NT) return;

    const float INF = __int_as_float(0x7f800000);
    float2 tc = *reinterpret_cast<const float2*>(tgt + t * 6 + 2);
    float2 ts = *reinterpret_cast<const float2*>(tgt + t * 6 + 4);
    const float tx = tc.x, ty = tc.y;
    const int tcx = min(G - 1, max(0, (int)(tx * CELLI)));
    const int tcy = min(G - 1, max(0, (int)(ty * CELLI)));

    // ---- gather 3x3 cell info: one aligned int2 count load per cell ----
    int cb[9]; int sa[9]; int pref[10];
    {
        int cnt[9];
        #pragma unroll
        for (int j = 0; j < 9; j++) {
            int x = tcx + (j % 3) - 1;
            int y = tcy + (j / 3) - 1;
            bool ok = (x >= 0) & (x < G) & (y >= 0) & (y < G);
            int c = ok ? (y * G + x) : 0;
            cb[j] = c * CAP;
            int2 q = ok ? __ldg(reinterpret_cast<const int2*>(g_count + c * R))
                        : make_int2(0, 0);
            int c0 = min(q.x, SUB), c1 = min(q.y, SUB);
            cnt[j] = c0 + c1;
            sa[j]  = c0;
        }
        pref[0] = 0;
        #pragma unroll
        for (int j = 0; j < 9; j++) pref[j + 1] = pref[j] + cnt[j];
    }
    const int T = pref[9];

    unsigned long long sel = ~0ull;
    bool stop = false;

    if (T <= 32 * CHUNK) {
        // ---- hot path: batched loads, lane sort, REDUX extraction ----
        unsigned long long key[CHUNK];
        {
            float4 pts[CHUNK]; bool val[CHUNK];
            auto mapLoad = [&](int c) {
                int v = c * 32 + lane;
                val[c] = (v < T);
                int basei = cb[0], pr = 0, a1 = sa[0];
                #pragma unroll
                for (int jj = 1; jj < 9; jj++) {
                    bool ge = (v >= pref[jj]);
                    basei = ge ? cb[jj]   : basei;
                    pr    = ge ? pref[jj] : pr;
                    a1    = ge ? sa[jj]   : a1;
                }
                int u = v - pr;
                int addr = basei + ((u >= a1) ? (SUB + u - a1) : u);
                if (val[c]) pts[c] = __ldg(&g_cells[addr]);   // independent LDGs, high MLP
            };
            #pragma unroll
            for (int c = 0; c < 5; c++) mapLoad(c);           // covers T <= 160 (91% of warps)
            if (T > 160) mapLoad(5); else val[5] = false;     // warp-uniform
            #pragma unroll
            for (int c = 0; c < CHUNK; c++) {
                if (val[c]) {
                    float dx = tx - pts[c].x;
                    float dy = ty - pts[c].y;
                    float d2 = fmaf(dy, dy, dx * dx);   // identical fp expr to verified kernels
                    key[c] = ((unsigned long long)__float_as_uint(d2) << 32)
                           | (unsigned)__float_as_int(pts[c].z);
                } else {
                    key[c] = ~0ull;                     // pad sorts last
                }
            }
        }

        // optimal 12-CE sorting network for 6 elements (ascending)
        auto CE = [&](int a, int b) {
            unsigned long long ka = key[a], kb = key[b];
            key[a] = ka < kb ? ka : kb;
            key[b] = ka < kb ? kb : ka;
        };
        CE(1,2); CE(4,5); CE(0,2); CE(3,5); CE(0,1); CE(3,4);
        CE(2,5); CE(0,3); CE(1,4); CE(2,4); CE(1,3); CE(2,3);

        // 9 extraction rounds: exact lex-min via two hardware REDUX.MIN ops
        unsigned D9bits = 0xFFFFFFFFu;
        #pragma unroll
        for (int r = 0; r < K; r++) {
            unsigned hi = (unsigned)(key[0] >> 32);
            unsigned lo = (unsigned)key[0];
            unsigned m1 = __reduce_min_sync(FULLMASK, hi);
            unsigned iv = (hi == m1) ? lo : 0xFFFFFFFFu;
            unsigned m2 = __reduce_min_sync(FULLMASK, iv);
            if (lane == r) sel = ((unsigned long long)m1 << 32) | m2;
            if (r == K - 1) D9bits = m1;
            if (hi == m1 && lo == m2) {     // unique owner for real keys
                #pragma unroll
                for (int j = 0; j < CHUNK - 1; j++) key[j] = key[j + 1];
                key[CHUNK - 1] = ~0ull;
            }
        }

        // r=1 stop bound (conservative). NaN/INF D9 -> stop stays false -> fallback.
        float D9 = __uint_as_float(D9bits);
        int x0 = max(tcx - 1, 0), x1 = min(tcx + 1, G - 1);
        int y0 = max(tcy - 1, 0), y1 = min(tcy + 1, G - 1);
        float m = INF;
        if (x0 > 0)     m = fminf(m, tx - (float)x0 * CELL);
        if (x1 < G - 1) m = fminf(m, (float)(x1 + 1) * CELL - tx);
        if (y0 > 0)     m = fminf(m, ty - (float)y0 * CELL);
        if (y1 < G - 1) m = fminf(m, (float)(y1 + 1) * CELL - ty);
        m *= 0.999f;
        stop = (m > 0.f && m * m > D9);
    }

    if (!stop) {
        // ---- fallback: box rescan from scratch, lane-per-cell (cold) ----
        float bd[K]; int bi[K];

        auto insertPt = [&](float4 c) {
            float dx = tx - c.x;
            float dy = ty - c.y;
            float d2 = fmaf(dy, dy, dx * dx);
            int   ci = __float_as_int(c.z);
            if (d2 < bd[K - 1] || (d2 == bd[K - 1] && ci < bi[K - 1])) {
                float cd = d2; int cj = ci;
                #pragma unroll
                for (int j = 0; j < K; j++) {
                    bool lt = (cd < bd[j]) || (cd == bd[j] && cj < bi[j]);
                    if (lt) {
                        float td = bd[j]; bd[j] = cd; cd = td;
                        int   ti = bi[j]; bi[j] = cj; cj = ti;
                    }
                }
            }
        };
        auto merge = [&]() {
            unsigned long long kk[K];
            #pragma unroll
            for (int j = 0; j < K; j++)
                kk[j] = ((unsigned long long)__float_as_uint(bd[j]) << 32) | (unsigned)bi[j];
            unsigned long long cur = kk[0];
            #pragma unroll
            for (int r = 0; r < K; r++) {
                unsigned long long mm = cur;
                #pragma unroll
                for (int o = 16; o; o >>= 1) {
                    unsigned long long v = __shfl_xor_sync(FULLMASK, mm, o);
                    if (v < mm) mm = v;
                }
                if (lane == r) sel = mm;
                if (cur == mm) {
                    #pragma unroll
                    for (int j = 0; j < K - 1; j++) kk[j] = kk[j + 1];
                    kk[K - 1] = ~0ull;
                    cur = kk[0];
                }
            }
        };

        for (int r = 2; ; r++) {
            int x0 = max(tcx - r, 0), x1 = min(tcx + r, G - 1);
            int y0 = max(tcy - r, 0), y1 = min(tcy + r, G - 1);
            int W = x1 - x0 + 1;
            int ncells = W * (y1 - y0 + 1);

            #pragma unroll
            for (int j = 0; j < K; j++) { bd[j] = INF; bi[j] = 0x7fffffff; }

            for (int cc = lane; cc < ncells; cc += 32) {
                int yy = y0 + cc / W;
                int xx = x0 + cc % W;
                int cell = yy * G + xx;
                int2 q = __ldg(reinterpret_cast<const int2*>(g_count + cell * R));
                const float4* bp = g_cells + cell * CAP;
                #pragma unroll
                for (int rr = 0; rr < R; rr++) {
                    int cn = min(rr == 0 ? q.x : q.y, SUB);
                    const float4* sp = bp + rr * SUB;
                    int s = 0;
                    for (; s + 2 <= cn; s += 2) {
                        float4 p0 = __ldg(sp + s);
                        float4 p1 = __ldg(sp + s + 1);
                        insertPt(p0); insertPt(p1);
                    }
                    for (; s < cn; s++) insertPt(__ldg(sp + s));
                }
            }

            merge();
            if (x0 == 0 && y0 == 0 && x1 == G - 1 && y1 == G - 1) break;  // full grid
            unsigned d9b = __shfl_sync(FULLMASK, (unsigned)(sel >> 32), 8);
            float D9f = __uint_as_float(d9b);
            float mf = INF;
            if (x0 > 0)     mf = fminf(mf, tx - (float)x0 * CELL);
            if (x1 < G - 1) mf = fminf(mf, (float)(x1 + 1) * CELL - tx);
            if (y0 > 0)     mf = fminf(mf, ty - (float)y0 * CELL);
            if (y1 < G - 1) mf = fminf(mf, (float)(y1 + 1) * CELL - ty);
            mf *= 0.999f;    // conservative margin; false on NaN/INF -> keep expanding
            if (mf > 0.f && mf * mf > D9f) break;
        }
    }

    // ---- epilogue gather (post-extraction, verified round-8 form) ----
    float cx = 0.f, cy = 0.f, cw_ = 0.f, ch_ = 0.f;
    if (lane < K) {
        int idx = (int)(sel & 0xffffffffull);
        float2 pc  = *reinterpret_cast<const float2*>(pbox + (size_t)idx * 6 + 2);
        float2 psz = *reinterpret_cast<const float2*>(pbox + (size_t)idx * 6 + 4);
        cx = pc.x; cy = pc.y; cw_ = psz.x; ch_ = psz.y;
    }

    // ---- epilogue: GIoU + mean/var(ddof=1) threshold (bit-identical fp order) ----
    float gx = tx, gy = ty;
    float gw = ts.x, gh = ts.y;

    float b1x1 = gx - gw * 0.5f, b1x2 = gx + gw * 0.5f;
    float b1y1 = gy - gh * 0.5f, b1y2 = gy + gh * 0.5f;
    float b2x1 = cx - cw_ * 0.5f, b2x2 = cx + cw_ * 0.5f;
    float b2y1 = cy - ch_ * 0.5f, b2y2 = cy + ch_ * 0.5f;
    float iw = fmaxf(fminf(b1x2, b2x2) - fmaxf(b1x1, b2x1), 0.f);
    float ih = fmaxf(fminf(b1y2, b2y2) - fmaxf(b1y1, b2y1), 0.f);
    float inter = iw * ih;
    float w1 = b1x2 - b1x1, h1 = b1y2 - b1y1;
    float w2 = b2x2 - b2x1, h2 = b2y2 - b2y1;
    float uni = ((w1 * h1 + 1e-16f) + w2 * h2) - inter;
    float iou = __fdiv_rn(inter, uni);
    float ccw = fmaxf(b1x2, b2x2) - fminf(b1x1, b2x1);
    float cch = fmaxf(b1y2, b2y2) - fminf(b1y1, b2y1);
    float carea = ccw * cch + 1e-16f;
    float g = iou - __fdiv_rn(carea - uni, carea);

    // mean: sequential 9-term sum, capturing each gj for reuse (same shfl values ->
    // same fp order as the verified two-loop form, but 9 shfls instead of 18)
    float gj[K];
    float s = 0.f;
    #pragma unroll
    for (int j = 0; j < K; j++) { gj[j] = __shfl_sync(FULLMASK, g, j); s += gj[j]; }
    float mean = __fdiv_rn(s, 9.0f);
    float v = 0.f;
    #pragma unroll
    for (int j = 0; j < K; j++) {
        float d = gj[j] - mean;
        v += d * d;
    }
    float var = __fdiv_rn(v, 8.0f);
    float thr = mean + var;

    if (lane < K) {
        float msk = (g > thr) ? 1.0f : 0.0f;
        float4 o = make_float4(cx * msk, cy * msk, cw_ * msk, ch_ * msk);
        *reinterpret_cast<float4*>(out + ((size_t)t * K + lane) * 4) = o;
    }
}

extern "C" void kernel_launch(void* const* d_in, const int* in_sizes, int n_in,
                              void* d_out, int out_size) {
    const float* pbox = (const float*)d_in[0];
    const float* tgt  = (const float*)d_in[1];
    int N  = in_sizes[0] / 6;
    int NT = in_sizes[1] / 6;

    void* cnt_ptr = nullptr;
    cudaGetSymbolAddress(&cnt_ptr, g_count);
    cudaMemsetAsync(cnt_ptr, 0, NC * R * sizeof(int));   // memset node, graph-capturable

    // 1024 blocks x 64 threads: all co-resident (required by the grid barrier),
    // covers N=65536 bin points one per thread and NT=2048 targets one per warp.
    int blocks = (NT + WARPS - 1) / WARPS;
    atss_fused_k<<<blocks, WARPS * 32>>>(pbox, tgt, (float*)d_out, N, NT);
}

// round 16
// speedup vs baseline: 1.1767x; 1.1499x over previous
#include <cuda_runtime.h>

#define FULLMASK 0xFFFFFFFFu

constexpr int   G     = 64;          // 64x64 grid of 16px cells
constexpr float CELL  = 16.0f;
constexpr float CELLI = 1.0f / 16.0f;
constexpr int   NC    = G * G;
constexpr int   R     = 2;           // replicated sub-counters per cell
constexpr int   SUB   = 40;          // capacity per replica; lambda=8 -> P(>40) ~ 1e-18
constexpr int   CAP   = R * SUB;     // 80 slots per cell
constexpr int   K     = 9;
constexpr int   WARPS = 2;           // warps per block (1 target per warp)
constexpr int   CHUNK = 6;           // 6*32 = 192 capacity; P(T>192) ~ 3e-5

__device__ int    g_count[NC * R];     // [cell][replica]
__device__ float4 g_cells[NC * CAP];   // x, y, bitcast(orig idx), pad

__global__ void bin_k(const float* __restrict__ p, int N) {
    int i = blockIdx.x * blockDim.x + threadIdx.x;
    if (i >= N) return;
    float2 c = reinterpret_cast<const float2*>(p)[i * 3 + 1];  // floats 6i+2, 6i+3
    int cx = min(G - 1, max(0, (int)(c.x * CELLI)));
    int cy = min(G - 1, max(0, (int)(c.y * CELLI)));
    int cell = cy * G + cx;
    int r = i & (R - 1);
    int pos = atomicAdd(&g_count[cell * R + r], 1);
    if (pos < SUB)
        g_cells[cell * CAP + r * SUB + pos] = make_float4(c.x, c.y, __int_as_float(i), 0.f);
}

__global__ __launch_bounds__(WARPS * 32, 8)
void atss_search_k(const float* __restrict__ pbox,
                   const float* __restrict__ tgt,
                   float* __restrict__ out, int NT)
{
    const int lane = threadIdx.x & 31;
    const int t = blockIdx.x * WARPS + (threadIdx.x >> 5);
    if (t >= NT) return;

    const float INF = __int_as_float(0x7f800000);
    float2 tc = *reinterpret_cast<const float2*>(tgt + t * 6 + 2);
    float2 ts = *reinterpret_cast<const float2*>(tgt + t * 6 + 4);
    const float tx = tc.x, ty = tc.y;
    const int tcx = min(G - 1, max(0, (int)(tx * CELLI)));
    const int tcy = min(G - 1, max(0, (int)(ty * CELLI)));

    // ---- gather 3x3 cell info: one aligned int2 count load per cell ----
    int cb[9]; int sa[9]; int pref[10];
    {
        int cnt[9];
        #pragma unroll
        for (int j = 0; j < 9; j++) {
            int x = tcx + (j % 3) - 1;
            int y = tcy + (j / 3) - 1;
            bool ok = (x >= 0) & (x < G) & (y >= 0) & (y < G);
            int c = ok ? (y * G + x) : 0;
            cb[j] = c * CAP;
            int2 q = ok ? __ldg(reinterpret_cast<const int2*>(g_count + c * R))
                        : make_int2(0, 0);
            int c0 = min(q.x, SUB), c1 = min(q.y, SUB);
            cnt[j] = c0 + c1;
            sa[j]  = c0;
        }
        pref[0] = 0;
        #pragma unroll
        for (int j = 0; j < 9; j++) pref[j + 1] = pref[j] + cnt[j];
    }
    const int T = pref[9];

    unsigned long long sel = ~0ull;
    bool stop = false;

    if (T <= 32 * CHUNK) {
        // ---- hot path: batched loads, lane sort, REDUX extraction ----
        unsigned long long key[CHUNK];
        {
            float4 pts[CHUNK]; bool val[CHUNK];
            auto mapLoad = [&](int c) {
                int v = c * 32 + lane;
                val[c] = (v < T);
                int basei = cb[0], pr = 0, a1 = sa[0];
                #pragma unroll
                for (int jj = 1; jj < 9; jj++) {
                    bool ge = (v >= pref[jj]);
                    basei = ge ? cb[jj]   : basei;
                    pr    = ge ? pref[jj] : pr;
                    a1    = ge ? sa[jj]   : a1;
                }
                int u = v - pr;
                int addr = basei + ((u >= a1) ? (SUB + u - a1) : u);
                if (val[c]) pts[c] = __ldg(&g_cells[addr]);   // independent LDGs, high MLP
            };
            #pragma unroll
            for (int c = 0; c < 5; c++) mapLoad(c);           // covers T <= 160 (91% of warps)
            if (T > 160) mapLoad(5); else val[5] = false;     // warp-uniform branch
            #pragma unroll
            for (int c = 0; c < CHUNK; c++) {
                if (val[c]) {
                    float dx = tx - pts[c].x;
                    float dy = ty - pts[c].y;
                    float d2 = fmaf(dy, dy, dx * dx);   // identical fp expr to verified kernels
                    key[c] = ((unsigned long long)__float_as_uint(d2) << 32)
                           | (unsigned)__float_as_int(pts[c].z);
                } else {
                    key[c] = ~0ull;                     // pad sorts last
                }
            }
        }

        // optimal 12-CE sorting network for 6 elements (ascending)
        auto CE = [&](int a, int b) {
            unsigned long long ka = key[a], kb = key[b];
            key[a] = ka < kb ? ka : kb;
            key[b] = ka < kb ? kb : ka;
        };
        CE(1,2); CE(4,5); CE(0,2); CE(3,5); CE(0,1); CE(3,4);
        CE(2,5); CE(0,3); CE(1,4); CE(2,4); CE(1,3); CE(2,3);

        // 9 extraction rounds: exact lex-min via two hardware REDUX.MIN ops
        unsigned D9bits = 0xFFFFFFFFu;
        #pragma unroll
        for (int r = 0; r < K; r++) {
            unsigned hi = (unsigned)(key[0] >> 32);
            unsigned lo = (unsigned)key[0];
            unsigned m1 = __reduce_min_sync(FULLMASK, hi);
            unsigned iv = (hi == m1) ? lo : 0xFFFFFFFFu;
            unsigned m2 = __reduce_min_sync(FULLMASK, iv);
            if (lane == r) sel = ((unsigned long long)m1 << 32) | m2;
            if (r == K - 1) D9bits = m1;
            if (hi == m1 && lo == m2) {     // unique owner for real keys
                #pragma unroll
                for (int j = 0; j < CHUNK - 1; j++) key[j] = key[j + 1];
                key[CHUNK - 1] = ~0ull;
            }
        }

        // r=1 stop bound (conservative). NaN/INF D9 -> stop stays false -> fallback.
        float D9 = __uint_as_float(D9bits);
        int x0 = max(tcx - 1, 0), x1 = min(tcx + 1, G - 1);
        int y0 = max(tcy - 1, 0), y1 = min(tcy + 1, G - 1);
        float m = INF;
        if (x0 > 0)     m = fminf(m, tx - (float)x0 * CELL);
        if (x1 < G - 1) m = fminf(m, (float)(x1 + 1) * CELL - tx);
        if (y0 > 0)     m = fminf(m, ty - (float)y0 * CELL);
        if (y1 < G - 1) m = fminf(m, (float)(y1 + 1) * CELL - ty);
        m *= 0.999f;
        stop = (m > 0.f && m * m > D9);
    }

    if (!stop) {
        // ---- fallback: box rescan from scratch, lane-per-cell (cold) ----
        float bd[K]; int bi[K];

        auto insertPt = [&](float4 c) {
            float dx = tx - c.x;
            float dy = ty - c.y;
            float d2 = fmaf(dy, dy, dx * dx);
            int   ci = __float_as_int(c.z);
            if (d2 < bd[K - 1] || (d2 == bd[K - 1] && ci < bi[K - 1])) {
                float cd = d2; int cj = ci;
                #pragma unroll
                for (int j = 0; j < K; j++) {
                    bool lt = (cd < bd[j]) || (cd == bd[j] && cj < bi[j]);
                    if (lt) {
                        float td = bd[j]; bd[j] = cd; cd = td;
                        int   ti = bi[j]; bi[j] = cj; cj = ti;
                    }
                }
            }
        };
        auto merge = [&]() {
            unsigned long long kk[K];
            #pragma unroll
            for (int j = 0; j < K; j++)
                kk[j] = ((unsigned long long)__float_as_uint(bd[j]) << 32) | (unsigned)bi[j];
            unsigned long long cur = kk[0];
            #pragma unroll
            for (int r = 0; r < K; r++) {
                unsigned long long mm = cur;
                #pragma unroll
                for (int o = 16; o; o >>= 1) {
                    unsigned long long v = __shfl_xor_sync(FULLMASK, mm, o);
                    if (v < mm) mm = v;
                }
                if (lane == r) sel = mm;
                if (cur == mm) {
                    #pragma unroll
                    for (int j = 0; j < K - 1; j++) kk[j] = kk[j + 1];
                    kk[K - 1] = ~0ull;
                    cur = kk[0];
                }
            }
        };

        for (int r = 2; ; r++) {
            int x0 = max(tcx - r, 0), x1 = min(tcx + r, G - 1);
            int y0 = max(tcy - r, 0), y1 = min(tcy + r, G - 1);
            int W = x1 - x0 + 1;
            int ncells = W * (y1 - y0 + 1);

            #pragma unroll
            for (int j = 0; j < K; j++) { bd[j] = INF; bi[j] = 0x7fffffff; }

            for (int cc = lane; cc < ncells; cc += 32) {
                int yy = y0 + cc / W;
                int xx = x0 + cc % W;
                int cell = yy * G + xx;
                int2 q = __ldg(reinterpret_cast<const int2*>(g_count + cell * R));
                const float4* bp = g_cells + cell * CAP;
                #pragma unroll
                for (int rr = 0; rr < R; rr++) {
                    int cn = min(rr == 0 ? q.x : q.y, SUB);
                    const float4* sp = bp + rr * SUB;
                    int s = 0;
                    for (; s + 2 <= cn; s += 2) {
                        float4 p0 = __ldg(sp + s);
                        float4 p1 = __ldg(sp + s + 1);
                        insertPt(p0); insertPt(p1);
                    }
                    for (; s < cn; s++) insertPt(__ldg(sp + s));
                }
            }

            merge();
            if (x0 == 0 && y0 == 0 && x1 == G - 1 && y1 == G - 1) break;  // full grid
            unsigned d9b = __shfl_sync(FULLMASK, (unsigned)(sel >> 32), 8);
            float D9f = __uint_as_float(d9b);
            float mf = INF;
            if (x0 > 0)     mf = fminf(mf, tx - (float)x0 * CELL);
            if (x1 < G - 1) mf = fminf(mf, (float)(x1 + 1) * CELL - tx);
            if (y0 > 0)     mf = fminf(mf, ty - (float)y0 * CELL);
            if (y1 < G - 1) mf = fminf(mf, (float)(y1 + 1) * CELL - ty);
            mf *= 0.999f;    // conservative margin; false on NaN/INF -> keep expanding
            if (mf > 0.f && mf * mf > D9f) break;
        }
    }

    // ---- epilogue gather (post-extraction, verified round-8 form) ----
    float cx = 0.f, cy = 0.f, cw_ = 0.f, ch_ = 0.f;
    if (lane < K) {
        int idx = (int)(sel & 0xffffffffull);
        float2 pc  = *reinterpret_cast<const float2*>(pbox + (size_t)idx * 6 + 2);
        float2 psz = *reinterpret_cast<const float2*>(pbox + (size_t)idx * 6 + 4);
        cx = pc.x; cy = pc.y; cw_ = psz.x; ch_ = psz.y;
    }

    // ---- epilogue: GIoU + mean/var(ddof=1) threshold (bit-identical fp order) ----
    float gx = tx, gy = ty;
    float gw = ts.x, gh = ts.y;

    float b1x1 = gx - gw * 0.5f, b1x2 = gx + gw * 0.5f;
    float b1y1 = gy - gh * 0.5f, b1y2 = gy + gh * 0.5f;
    float b2x1 = cx - cw_ * 0.5f, b2x2 = cx + cw_ * 0.5f;
    float b2y1 = cy - ch_ * 0.5f, b2y2 = cy + ch_ * 0.5f;
    float iw = fmaxf(fminf(b1x2, b2x2) - fmaxf(b1x1, b2x1), 0.f);
    float ih = fmaxf(fminf(b1y2, b2y2) - fmaxf(b1y1, b2y1), 0.f);
    float inter = iw * ih;
    float w1 = b1x2 - b1x1, h1 = b1y2 - b1y1;
    float w2 = b2x2 - b2x1, h2 = b2y2 - b2y1;
    float uni = ((w1 * h1 + 1e-16f) + w2 * h2) - inter;
    float iou = __fdiv_rn(inter, uni);
    float ccw = fmaxf(b1x2, b2x2) - fminf(b1x1, b2x1);
    float cch = fmaxf(b1y2, b2y2) - fminf(b1y1, b2y1);
    float carea = ccw * cch + 1e-16f;
    float g = iou - __fdiv_rn(carea - uni, carea);

    // mean: 9-term sequential sum, capturing each gj for the var loop (same shfl
    // values -> same fp order as the verified two-loop form; 9 shfls not 18)
    float gj[K];
    float s = 0.f;
    #pragma unroll
    for (int j = 0; j < K; j++) { gj[j] = __shfl_sync(FULLMASK, g, j); s += gj[j]; }
    float mean = __fdiv_rn(s, 9.0f);
    float v = 0.f;
    #pragma unroll
    for (int j = 0; j < K; j++) {
        float d = gj[j] - mean;
        v += d * d;
    }
    float var = __fdiv_rn(v, 8.0f);
    float thr = mean + var;

    if (lane < K) {
        float msk = (g > thr) ? 1.0f : 0.0f;
        float4 o = make_float4(cx * msk, cy * msk, cw_ * msk, ch_ * msk);
        *reinterpret_cast<float4*>(out + ((size_t)t * K + lane) * 4) = o;
    }
}

extern "C" void kernel_launch(void* const* d_in, const int* in_sizes, int n_in,
                              void* d_out, int out_size) {
    const float* pbox = (const float*)d_in[0];
    const float* tgt  = (const float*)d_in[1];
    int N  = in_sizes[0] / 6;
    int NT = in_sizes[1] / 6;

    void* cnt_ptr = nullptr;
    cudaGetSymbolAddress(&cnt_ptr, g_count);
    cudaMemsetAsync(cnt_ptr, 0, NC * R * sizeof(int));   // memset node, graph-capturable

    bin_k<<<(N + 255) / 256, 256>>>(pbox, N);

    int blocks = (NT + WARPS - 1) / WARPS;
    atss_search_k<<<blocks, WARPS * 32>>>(pbox, tgt, (float*)d_out, NT);
}

// round 17
// speedup vs baseline: 1.2644x; 1.0745x over previous
#include <cuda_runtime.h>

#define FULLMASK 0xFFFFFFFFu

constexpr int   G     = 64;          // 64x64 grid of 16px cells
constexpr float CELL  = 16.0f;
constexpr float CELLI = 1.0f / 16.0f;
constexpr int   NC    = G * G;
constexpr int   SUB   = 64;          // slots per cell (R=1); lambda=16 -> P(>64) ~ 1e-19
constexpr int   K     = 9;
constexpr int   WARPS = 2;           // warps per block (1 target per warp)
constexpr int   BLIND = 24;          // blind-loaded slots per cell (counts-independent)
constexpr int   BCH   = 7;           // blind chunks: 9*24=216 <= 7*32=224
constexpr int   NKEY  = 8;           // 7 blind + 1 overflow key slots per lane

__device__ int    g_count[NC];         // per-cell count
__device__ float4 g_cells[NC * SUB];   // x, y, bitcast(orig idx), pad

__global__ void bin_k(const float* __restrict__ p, int N) {
    int i = blockIdx.x * blockDim.x + threadIdx.x;
    if (i >= N) return;
    float2 c = reinterpret_cast<const float2*>(p)[i * 3 + 1];  // floats 6i+2, 6i+3
    int cx = min(G - 1, max(0, (int)(c.x * CELLI)));
    int cy = min(G - 1, max(0, (int)(c.y * CELLI)));
    int cell = cy * G + cx;
    int pos = atomicAdd(&g_count[cell], 1);
    if (pos < SUB)
        g_cells[cell * SUB + pos] = make_float4(c.x, c.y, __int_as_float(i), 0.f);
}

__global__ __launch_bounds__(WARPS * 32, 8)
void atss_search_k(const float* __restrict__ pbox,
                   const float* __restrict__ tgt,
                   float* __restrict__ out, int NT)
{
    const int lane = threadIdx.x & 31;
    const int t = blockIdx.x * WARPS + (threadIdx.x >> 5);
    if (t >= NT) return;

    const float INF = __int_as_float(0x7f800000);
    float2 tc = *reinterpret_cast<const float2*>(tgt + t * 6 + 2);
    float2 ts = *reinterpret_cast<const float2*>(tgt + t * 6 + 4);
    const float tx = tc.x, ty = tc.y;
    const int tcx = min(G - 1, max(0, (int)(tx * CELLI)));
    const int tcy = min(G - 1, max(0, (int)(ty * CELLI)));

    // ---- 3x3 cell bases + counts. Blind point loads below do NOT depend on the
    // count values, so ALL loads (9 counts + 216 points) go out in ONE trip. ----
    int cb[9]; int cnt[9];
    #pragma unroll
    for (int j = 0; j < 9; j++) {
        int x = tcx + (j % 3) - 1;
        int y = tcy + (j / 3) - 1;
        bool ok = (x >= 0) & (x < G) & (y >= 0) & (y < G);
        int c = ok ? (y * G + x) : 0;
        cb[j]  = c * SUB;
        cnt[j] = ok ? min(__ldg(&g_count[c]), SUB) : 0;
    }

    unsigned long long key[NKEY];

    // ---- blind phase: slots 0..BLIND-1 of each cell; validity = pos < cnt.
    // (Also rejects stale slots beyond count left by earlier replays.) ----
    {
        float4 pts[BCH]; bool val[BCH]; int idxv[BCH];
        #pragma unroll
        for (int c = 0; c < BCH; c++) {
            int v = c * 32 + lane;                  // virtual blind index, 0..223
            const int j0  = (32 * c) / BLIND;       // compile-time per chunk
            const int bnd = BLIND * (j0 + 1);
            const int jhi = (j0 + 1 > 8) ? 8 : j0 + 1;   // clamp (c=6 hi is invalid anyway)
            bool isHi = (v >= bnd);
            int pos   = v - (isHi ? bnd : BLIND * j0);
            int cbs   = isHi ? cb[jhi]  : cb[j0];   // static 2-way selects
            int cns   = isHi ? cnt[jhi] : cnt[j0];
            val[c] = (pos < cns) && (v < 9 * BLIND);
            if (val[c]) pts[c] = __ldg(&g_cells[cbs + pos]);   // independent LDGs
        }
        #pragma unroll
        for (int c = 0; c < BCH; c++) {
            if (val[c]) {
                float dx = tx - pts[c].x;
                float dy = ty - pts[c].y;
                float d2 = fmaf(dy, dy, dx * dx);   // identical fp expr to verified kernels
                key[c] = ((unsigned long long)__float_as_uint(d2) << 32)
                       | (unsigned)__float_as_int(pts[c].z);
            } else {
                key[c] = ~0ull;                     // pad sorts last
            }
        }
        (void)idxv;
    }

    // ---- overflow phase: slots BLIND..cnt-1 (E[total] ~ 0.5 points) ----
    int oc[9]; int pref[10];
    pref[0] = 0;
    #pragma unroll
    for (int j = 0; j < 9; j++) {
        oc[j] = max(cnt[j] - BLIND, 0);
        pref[j + 1] = pref[j] + oc[j];
    }
    const int Tov = pref[9];
    bool hot = (Tov <= 32);
    key[7] = ~0ull;
    if (hot && Tov > 0) {                 // warp-uniform (~18% of warps)
        int v = lane;
        bool valid = (v < Tov);
        int basei = cb[0], pr = 0;
        #pragma unroll
        for (int jj = 1; jj < 9; jj++) {
            bool ge = (v >= pref[jj]);
            basei = ge ? cb[jj]   : basei;
            pr    = ge ? pref[jj] : pr;
        }
        if (valid) {
            float4 p = __ldg(&g_cells[basei + BLIND + (v - pr)]);
            float dx = tx - p.x;
            float dy = ty - p.y;
            float d2 = fmaf(dy, dy, dx * dx);
            key[7] = ((unsigned long long)__float_as_uint(d2) << 32)
                   | (unsigned)__float_as_int(p.z);
        }
    }

    unsigned long long sel = ~0ull;
    bool stop = false;

    if (hot) {
        // Batcher odd-even mergesort network for 8 elements (19 CE, ascending)
        auto CE = [&](int a, int b) {
            unsigned long long ka = key[a], kb = key[b];
            key[a] = ka < kb ? ka : kb;
            key[b] = ka < kb ? kb : ka;
        };
        CE(0,1); CE(2,3); CE(4,5); CE(6,7);
        CE(0,2); CE(1,3); CE(4,6); CE(5,7);
        CE(1,2); CE(5,6);
        CE(0,4); CE(1,5); CE(2,6); CE(3,7);
        CE(2,4); CE(3,5);
        CE(1,2); CE(3,4); CE(5,6);

        // 9 extraction rounds: exact lex-min via two hardware REDUX.MIN ops
        unsigned D9bits = 0xFFFFFFFFu;
        #pragma unroll
        for (int r = 0; r < K; r++) {
            unsigned hi = (unsigned)(key[0] >> 32);
            unsigned lo = (unsigned)key[0];
            unsigned m1 = __reduce_min_sync(FULLMASK, hi);
            unsigned iv = (hi == m1) ? lo : 0xFFFFFFFFu;
            unsigned m2 = __reduce_min_sync(FULLMASK, iv);
            if (lane == r) sel = ((unsigned long long)m1 << 32) | m2;
            if (r == K - 1) D9bits = m1;
            if (hi == m1 && lo == m2) {     // unique owner for real keys
                #pragma unroll
                for (int j = 0; j < NKEY - 1; j++) key[j] = key[j + 1];
                key[NKEY - 1] = ~0ull;
            }
        }

        // r=1 stop bound (conservative). NaN/INF D9 -> stop stays false -> fallback.
        float D9 = __uint_as_float(D9bits);
        int x0 = max(tcx - 1, 0), x1 = min(tcx + 1, G - 1);
        int y0 = max(tcy - 1, 0), y1 = min(tcy + 1, G - 1);
        float m = INF;
        if (x0 > 0)     m = fminf(m, tx - (float)x0 * CELL);
        if (x1 < G - 1) m = fminf(m, (float)(x1 + 1) * CELL - tx);
        if (y0 > 0)     m = fminf(m, ty - (float)y0 * CELL);
        if (y1 < G - 1) m = fminf(m, (float)(y1 + 1) * CELL - ty);
        m *= 0.999f;
        stop = (m > 0.f && m * m > D9);
    }

    if (!stop) {
        // ---- fallback: box rescan from scratch, lane-per-cell (cold, verified) ----
        float bd[K]; int bi[K];

        auto insertPt = [&](float4 c) {
            float dx = tx - c.x;
            float dy = ty - c.y;
            float d2 = fmaf(dy, dy, dx * dx);
            int   ci = __float_as_int(c.z);
            if (d2 < bd[K - 1] || (d2 == bd[K - 1] && ci < bi[K - 1])) {
                float cd = d2; int cj = ci;
                #pragma unroll
                for (int j = 0; j < K; j++) {
                    bool lt = (cd < bd[j]) || (cd == bd[j] && cj < bi[j]);
                    if (lt) {
                        float td = bd[j]; bd[j] = cd; cd = td;
                        int   ti = bi[j]; bi[j] = cj; cj = ti;
                    }
                }
            }
        };
        auto merge = [&]() {
            unsigned long long kk[K];
            #pragma unroll
            for (int j = 0; j < K; j++)
                kk[j] = ((unsigned long long)__float_as_uint(bd[j]) << 32) | (unsigned)bi[j];
            unsigned long long cur = kk[0];
            #pragma unroll
            for (int r = 0; r < K; r++) {
                unsigned long long mm = cur;
                #pragma unroll
                for (int o = 16; o; o >>= 1) {
                    unsigned long long v = __shfl_xor_sync(FULLMASK, mm, o);
                    if (v < mm) mm = v;
                }
                if (lane == r) sel = mm;
                if (cur == mm) {
                    #pragma unroll
                    for (int j = 0; j < K - 1; j++) kk[j] = kk[j + 1];
                    kk[K - 1] = ~0ull;
                    cur = kk[0];
                }
            }
        };

        for (int r = 2; ; r++) {
            int x0 = max(tcx - r, 0), x1 = min(tcx + r, G - 1);
            int y0 = max(tcy - r, 0), y1 = min(tcy + r, G - 1);
            int W = x1 - x0 + 1;
            int ncells = W * (y1 - y0 + 1);

            #pragma unroll
            for (int j = 0; j < K; j++) { bd[j] = INF; bi[j] = 0x7fffffff; }

            for (int cc = lane; cc < ncells; cc += 32) {
                int yy = y0 + cc / W;
                int xx = x0 + cc % W;
                int cell = yy * G + xx;
                int cn = min(__ldg(&g_count[cell]), SUB);
                const float4* sp = g_cells + cell * SUB;
                int s = 0;
                for (; s + 2 <= cn; s += 2) {
                    float4 p0 = __ldg(sp + s);
                    float4 p1 = __ldg(sp + s + 1);
                    insertPt(p0); insertPt(p1);
                }
                for (; s < cn; s++) insertPt(__ldg(sp + s));
            }

            merge();
            if (x0 == 0 && y0 == 0 && x1 == G - 1 && y1 == G - 1) break;  // full grid
            unsigned d9b = __shfl_sync(FULLMASK, (unsigned)(sel >> 32), 8);
            float D9f = __uint_as_float(d9b);
            float mf = INF;
            if (x0 > 0)     mf = fminf(mf, tx - (float)x0 * CELL);
            if (x1 < G - 1) mf = fminf(mf, (float)(x1 + 1) * CELL - tx);
            if (y0 > 0)     mf = fminf(mf, ty - (float)y0 * CELL);
            if (y1 < G - 1) mf = fminf(mf, (float)(y1 + 1) * CELL - ty);
            mf *= 0.999f;    // conservative margin; false on NaN/INF -> keep expanding
            if (mf > 0.f && mf * mf > D9f) break;
        }
    }

    // ---- epilogue gather (post-extraction, verified round-8 form) ----
    float cx = 0.f, cy = 0.f, cw_ = 0.f, ch_ = 0.f;
    if (lane < K) {
        int idx = (int)(sel & 0xffffffffull);
        float2 pc  = *reinterpret_cast<const float2*>(pbox + (size_t)idx * 6 + 2);
        float2 psz = *reinterpret_cast<const float2*>(pbox + (size_t)idx * 6 + 4);
        cx = pc.x; cy = pc.y; cw_ = psz.x; ch_ = psz.y;
    }

    // ---- epilogue: GIoU + mean/var(ddof=1) threshold (bit-identical fp order) ----
    float gx = tx, gy = ty;
    float gw = ts.x, gh = ts.y;

    float b1x1 = gx - gw * 0.5f, b1x2 = gx + gw * 0.5f;
    float b1y1 = gy - gh * 0.5f, b1y2 = gy + gh * 0.5f;
    float b2x1 = cx - cw_ * 0.5f, b2x2 = cx + cw_ * 0.5f;
    float b2y1 = cy - ch_ * 0.5f, b2y2 = cy + ch_ * 0.5f;
    float iw = fmaxf(fminf(b1x2, b2x2) - fmaxf(b1x1, b2x1), 0.f);
    float ih = fmaxf(fminf(b1y2, b2y2) - fmaxf(b1y1, b2y1), 0.f);
    float inter = iw * ih;
    float w1 = b1x2 - b1x1, h1 = b1y2 - b1y1;
    float w2 = b2x2 - b2x1, h2 = b2y2 - b2y1;
    float uni = ((w1 * h1 + 1e-16f) + w2 * h2) - inter;
    float iou = __fdiv_rn(inter, uni);
    float ccw = fmaxf(b1x2, b2x2) - fminf(b1x1, b2x1);
    float cch = fmaxf(b1y2, b2y2) - fminf(b1y1, b2y1);
    float carea = ccw * cch + 1e-16f;
    float g = iou - __fdiv_rn(carea - uni, carea);

    // mean: 9-term sequential sum, capturing each gj for the var loop (same shfl
    // values -> same fp order as the verified two-loop form; 9 shfls not 18)
    float gj[K];
    float s = 0.f;
    #pragma unroll
    for (int j = 0; j < K; j++) { gj[j] = __shfl_sync(FULLMASK, g, j); s += gj[j]; }
    float mean = __fdiv_rn(s, 9.0f);
    float v = 0.f;
    #pragma unroll
    for (int j = 0; j < K; j++) {
        float d = gj[j] - mean;
        v += d * d;
    }
    float var = __fdiv_rn(v, 8.0f);
    float thr = mean + var;

    if (lane < K) {
        float msk = (g > thr) ? 1.0f : 0.0f;
        float4 o = make_float4(cx * msk, cy * msk, cw_ * msk, ch_ * msk);
        *reinterpret_cast<float4*>(out + ((size_t)t * K + lane) * 4) = o;
    }
}

extern "C" void kernel_launch(void* const* d_in, const int* in_sizes, int n_in,
                              void* d_out, int out_size) {
    const float* pbox = (const float*)d_in[0];
    const float* tgt  = (const float*)d_in[1];
    int N  = in_sizes[0] / 6;
    int NT = in_sizes[1] / 6;

    void* cnt_ptr = nullptr;
    cudaGetSymbolAddress(&cnt_ptr, g_count);
    cudaMemsetAsync(cnt_ptr, 0, NC * sizeof(int));   // memset node, graph-capturable

    bin_k<<<(N + 255) / 256, 256>>>(pbox, N);

    int blocks = (NT + WARPS - 1) / WARPS;
    atss_search_k<<<blocks, WARPS * 32>>>(pbox, tgt, (float*)d_out, NT);
}